// round 8
// baseline (speedup 1.0000x reference)
#include <cuda_runtime.h>
#include <cuda_bf16.h>

#define WEIGHT_POSITIVE 0.1f

// 148 SMs x 8 CTAs/SM = one balanced wave.
static constexpr int BLOCKS  = 148 * 8;   // 1184
static constexpr int THREADS = 256;

// Scratch (no device allocation allowed anywhere).
__device__ float        g_partials[BLOCKS];
__device__ unsigned int g_ticket = 0;

__device__ __forceinline__ float elem(float p, int t)
{
    float d   = p - (float)t;
    bool  mis = (p >= 0.5f) != (t == 1);
    return (mis ? (1.0f + WEIGHT_POSITIVE) : 1.0f) * d * d;
}

__device__ __forceinline__ float quad(float4 p, int4 t)
{
    return (elem(p.x, t.x) + elem(p.y, t.y)) + (elem(p.z, t.z) + elem(p.w, t.w));
}

__global__ __launch_bounds__(THREADS, 8)
void wmse_fused_kernel(const float4* __restrict__ pred4,
                       const int4*   __restrict__ tgt4,
                       float* __restrict__ out,
                       int n_vec, float inv_n)
{
    const int tid = threadIdx.x;

    // Block-tiled x2: each block consumes contiguous chunks of 2*THREADS float4s.
    // Per thread: 4 front-batched LDG.128s, all within an 8KB window -> MLP=4
    // with good DRAM locality (unlike the failed 4MB-spaced unroll).
    const int gstride = gridDim.x * THREADS * 2;
    int chunk = blockIdx.x * THREADS * 2;

    float s0 = 0.0f, s1 = 0.0f;
    for (; chunk + THREADS * 2 <= n_vec; chunk += gstride) {
        int i0 = chunk + tid;
        int i1 = chunk + THREADS + tid;
        float4 p0 = __ldg(&pred4[i0]);
        float4 p1 = __ldg(&pred4[i1]);
        int4   t0 = __ldg(&tgt4[i0]);
        int4   t1 = __ldg(&tgt4[i1]);
        s0 += quad(p0, t0);
        s1 += quad(p1, t1);
    }
    // Tail (generic-n safety; n_vec = 2^23 divides evenly so normally empty).
    for (int i = chunk + tid; i < n_vec; i += THREADS)
        s0 += quad(__ldg(&pred4[i]), __ldg(&tgt4[i]));

    float sum = s0 + s1;

    // Warp reduce
    #pragma unroll
    for (int off = 16; off > 0; off >>= 1)
        sum += __shfl_down_sync(0xFFFFFFFFu, sum, off);

    __shared__ float warp_sums[THREADS / 32];
    __shared__ bool  is_last;
    int lane = threadIdx.x & 31;
    int wid  = threadIdx.x >> 5;
    if (lane == 0) warp_sums[wid] = sum;
    __syncthreads();

    if (wid == 0) {
        float s = (lane < THREADS / 32) ? warp_sums[lane] : 0.0f;
        #pragma unroll
        for (int off = 16; off > 0; off >>= 1)
            s += __shfl_down_sync(0xFFFFFFFFu, s, off);
        if (lane == 0) {
            g_partials[blockIdx.x] = s;
            __threadfence();
            unsigned int t = atomicAdd(&g_ticket, 1u);
            is_last = (t == (unsigned int)(gridDim.x - 1));
        }
    }
    __syncthreads();

    // Last block to finish sums all partials in a FIXED order -> deterministic.
    if (is_last) {
        float fs = 0.0f;
        for (int k = threadIdx.x; k < BLOCKS; k += THREADS)
            fs += *((volatile float*)&g_partials[k]);

        #pragma unroll
        for (int off = 16; off > 0; off >>= 1)
            fs += __shfl_down_sync(0xFFFFFFFFu, fs, off);

        if (lane == 0) warp_sums[wid] = fs;
        __syncthreads();

        if (wid == 0) {
            float s = (lane < THREADS / 32) ? warp_sums[lane] : 0.0f;
            #pragma unroll
            for (int off = 16; off > 0; off >>= 1)
                s += __shfl_down_sync(0xFFFFFFFFu, s, off);
            if (lane == 0) {
                out[0] = s * inv_n;
                g_ticket = 0;   // reset for next graph replay (deterministic)
            }
        }
    }
}

extern "C" void kernel_launch(void* const* d_in, const int* in_sizes, int n_in,
                              void* d_out, int out_size)
{
    const float* pred = (const float*)d_in[0];
    const int*   tgt  = (const int*)d_in[1];
    float*       out  = (float*)d_out;
    int n = in_sizes[0];

    int n_vec = n / 4;  // N = 2^25, divisible by 4

    wmse_fused_kernel<<<BLOCKS, THREADS>>>((const float4*)pred, (const int4*)tgt,
                                           out, n_vec, 1.0f / (float)n);
}

// round 9
// speedup vs baseline: 1.0410x; 1.0410x over previous
#include <cuda_runtime.h>
#include <cuda_bf16.h>

#define WEIGHT_POSITIVE 0.1f

// 148 SMs x 8 CTAs/SM = one balanced wave.
static constexpr int BLOCKS  = 148 * 8;   // 1184
static constexpr int THREADS = 256;

// Scratch (no device allocation allowed anywhere).
__device__ float g_partials[BLOCKS];

__device__ __forceinline__ float elem(float p, int t)
{
    float d   = p - (float)t;
    bool  mis = (p >= 0.5f) != (t == 1);
    return (mis ? (1.0f + WEIGHT_POSITIVE) : 1.0f) * d * d;
}

__global__ __launch_bounds__(THREADS)
void wmse_partial_kernel(const float4* __restrict__ pred4,
                         const int4*   __restrict__ tgt4,
                         int n_vec)
{
    const int stride = gridDim.x * blockDim.x;

    float sum = 0.0f;
    for (int i = blockIdx.x * blockDim.x + threadIdx.x; i < n_vec; i += stride) {
        float4 p = __ldg(&pred4[i]);
        int4   t = __ldg(&tgt4[i]);
        sum += elem(p.x, t.x) + elem(p.y, t.y) + elem(p.z, t.z) + elem(p.w, t.w);
    }

    // Warp reduce
    #pragma unroll
    for (int off = 16; off > 0; off >>= 1)
        sum += __shfl_down_sync(0xFFFFFFFFu, sum, off);

    __shared__ float warp_sums[THREADS / 32];
    int lane = threadIdx.x & 31;
    int wid  = threadIdx.x >> 5;
    if (lane == 0) warp_sums[wid] = sum;
    __syncthreads();

    if (wid == 0) {
        float s = (lane < THREADS / 32) ? warp_sums[lane] : 0.0f;
        #pragma unroll
        for (int off = 16; off > 0; off >>= 1)
            s += __shfl_down_sync(0xFFFFFFFFu, s, off);
        if (lane == 0)
            g_partials[blockIdx.x] = s;
    }

    // Let the dependent (PDL) final kernel launch as early as possible.
    cudaTriggerProgrammaticLaunchCompletion();
}

__global__ __launch_bounds__(THREADS)
void wmse_final_kernel(float* __restrict__ out, float inv_n)
{
    // PDL: launched concurrently with the primary; this blocks until the
    // primary kernel's memory (g_partials) is visible. Launch latency is
    // hidden behind the primary's execution.
    cudaGridDependencySynchronize();

    float sum = 0.0f;
    for (int i = threadIdx.x; i < BLOCKS; i += THREADS)
        sum += __ldcg(&g_partials[i]);

    #pragma unroll
    for (int off = 16; off > 0; off >>= 1)
        sum += __shfl_down_sync(0xFFFFFFFFu, sum, off);

    __shared__ float warp_sums[THREADS / 32];
    int lane = threadIdx.x & 31;
    int wid  = threadIdx.x >> 5;
    if (lane == 0) warp_sums[wid] = sum;
    __syncthreads();

    if (wid == 0) {
        float s = (lane < THREADS / 32) ? warp_sums[lane] : 0.0f;
        #pragma unroll
        for (int off = 16; off > 0; off >>= 1)
            s += __shfl_down_sync(0xFFFFFFFFu, s, off);
        if (lane == 0) out[0] = s * inv_n;
    }
}

extern "C" void kernel_launch(void* const* d_in, const int* in_sizes, int n_in,
                              void* d_out, int out_size)
{
    const float* pred = (const float*)d_in[0];
    const int*   tgt  = (const int*)d_in[1];
    float*       out  = (float*)d_out;
    int n = in_sizes[0];

    int n_vec = n / 4;  // N = 2^25, divisible by 4

    wmse_partial_kernel<<<BLOCKS, THREADS>>>((const float4*)pred, (const int4*)tgt, n_vec);

    // Final reduce with Programmatic Dependent Launch: hides its launch latency
    // behind the primary kernel's execution.
    cudaLaunchConfig_t cfg = {};
    cfg.gridDim  = dim3(1, 1, 1);
    cfg.blockDim = dim3(THREADS, 1, 1);
    cfg.dynamicSmemBytes = 0;
    cfg.stream = 0;  // same (capture) stream as the <<<>>> launch above

    cudaLaunchAttribute attr;
    attr.id = cudaLaunchAttributeProgrammaticStreamSerialization;
    attr.val.programmaticStreamSerializationAllowed = 1;
    cfg.attrs = &attr;
    cfg.numAttrs = 1;

    cudaLaunchKernelEx(&cfg, wmse_final_kernel, out, 1.0f / (float)n);
}

// round 12
// speedup vs baseline: 1.0462x; 1.0050x over previous
#include <cuda_runtime.h>
#include <cuda_bf16.h>
#include <cstdint>

#define WEIGHT_POSITIVE 0.1f

static constexpr int THREADS   = 256;
static constexpr int BLOCKS    = 148 * 2;          // 296: 2 CTAs/SM
static constexpr int TILE_V4   = 512;              // 512 float4 = 8KB per array per tile
static constexpr int TILE_B    = TILE_V4 * 16;     // 8192 bytes
static constexpr int DEPTH     = 4;                // pipeline stages

// dynamic smem layout:
// [0, 128)                      : DEPTH mbarriers (8B each) + pad
// [128, 128+DEPTH*8KB)          : pred tiles
// [.., +DEPTH*8KB)              : tgt tiles
static constexpr int SM_MBAR   = 0;
static constexpr int SM_PRED   = 128;
static constexpr int SM_TGT    = SM_PRED + DEPTH * TILE_B;
static constexpr int SMEM_SIZE = SM_TGT + DEPTH * TILE_B;   // 128 + 64KB

// Scratch (no device allocation allowed anywhere).
__device__ float        g_partials[BLOCKS];
__device__ unsigned int g_ticket = 0;

__device__ __forceinline__ float elem(float p, int t)
{
    float d   = p - (float)t;
    bool  mis = (p >= 0.5f) != (t == 1);
    return (mis ? (1.0f + WEIGHT_POSITIVE) : 1.0f) * d * d;
}

__device__ __forceinline__ float quad(float4 p, int4 t)
{
    return (elem(p.x, t.x) + elem(p.y, t.y)) + (elem(p.z, t.z) + elem(p.w, t.w));
}

__device__ __forceinline__ void mbar_init(uint32_t addr, uint32_t count)
{
    asm volatile("mbarrier.init.shared.b64 [%0], %1;" :: "r"(addr), "r"(count) : "memory");
}

__device__ __forceinline__ void mbar_expect_tx(uint32_t addr, uint32_t bytes)
{
    asm volatile("mbarrier.arrive.expect_tx.shared.b64 _, [%0], %1;"
                 :: "r"(addr), "r"(bytes) : "memory");
}

__device__ __forceinline__ void mbar_wait(uint32_t addr, uint32_t parity)
{
    asm volatile(
        "{\n\t"
        ".reg .pred P;\n\t"
        "WAIT_%=:\n\t"
        "mbarrier.try_wait.parity.acquire.cta.shared::cta.b64 P, [%0], %1, 0x989680;\n\t"
        "@P bra.uni DONE_%=;\n\t"
        "bra.uni WAIT_%=;\n\t"
        "DONE_%=:\n\t"
        "}"
        :: "r"(addr), "r"(parity) : "memory");
}

__device__ __forceinline__ void bulk_copy(uint32_t smem_dst, const void* gmem_src,
                                          uint32_t bytes, uint32_t mbar)
{
    asm volatile(
        "cp.async.bulk.shared::cluster.global.mbarrier::complete_tx::bytes "
        "[%0], [%1], %2, [%3];"
        :: "r"(smem_dst), "l"(gmem_src), "r"(bytes), "r"(mbar) : "memory");
}

__global__ __launch_bounds__(THREADS)
void wmse_bulk_kernel(const float4* __restrict__ pred4,
                      const int4*   __restrict__ tgt4,
                      float* __restrict__ out,
                      int n_tiles, float inv_n)
{
    extern __shared__ char smem[];
    const uint32_t sbase = (uint32_t)__cvta_generic_to_shared(smem);
    const int tid = threadIdx.x;

    // Number of tiles this CTA owns (round-robin by gridDim).
    int my_tiles = (n_tiles - (int)blockIdx.x + (int)gridDim.x - 1) / (int)gridDim.x;

    if (tid == 0) {
        #pragma unroll
        for (int s = 0; s < DEPTH; s++)
            mbar_init(sbase + SM_MBAR + s * 8, 1);
    }
    __syncthreads();

    // Prologue: issue first DEPTH tiles.
    if (tid == 0) {
        #pragma unroll
        for (int s = 0; s < DEPTH; s++) {
            if (s < my_tiles) {
                long g = (long)blockIdx.x + (long)s * gridDim.x;   // global tile id
                uint32_t mb = sbase + SM_MBAR + s * 8;
                mbar_expect_tx(mb, 2 * TILE_B);
                bulk_copy(sbase + SM_PRED + s * TILE_B, pred4 + g * TILE_V4, TILE_B, mb);
                bulk_copy(sbase + SM_TGT  + s * TILE_B, tgt4  + g * TILE_V4, TILE_B, mb);
            }
        }
    }

    float sum = 0.0f;
    for (int k = 0; k < my_tiles; k++) {
        int s = k % DEPTH;
        uint32_t ph = (uint32_t)((k / DEPTH) & 1);
        uint32_t mb = sbase + SM_MBAR + s * 8;
        mbar_wait(mb, ph);

        const float4* ps = (const float4*)(smem + SM_PRED + s * TILE_B);
        const int4*   ts = (const int4*)  (smem + SM_TGT  + s * TILE_B);

        float4 p0 = ps[tid];
        float4 p1 = ps[tid + THREADS];
        int4   t0 = ts[tid];
        int4   t1 = ts[tid + THREADS];
        sum += quad(p0, t0) + quad(p1, t1);

        __syncthreads();   // all reads of slot s done before refill

        if (tid == 0 && k + DEPTH < my_tiles) {
            long g = (long)blockIdx.x + (long)(k + DEPTH) * gridDim.x;
            mbar_expect_tx(mb, 2 * TILE_B);
            bulk_copy(sbase + SM_PRED + s * TILE_B, pred4 + g * TILE_V4, TILE_B, mb);
            bulk_copy(sbase + SM_TGT  + s * TILE_B, tgt4  + g * TILE_V4, TILE_B, mb);
        }
    }

    // Warp reduce
    #pragma unroll
    for (int off = 16; off > 0; off >>= 1)
        sum += __shfl_down_sync(0xFFFFFFFFu, sum, off);

    __shared__ float warp_sums[THREADS / 32];
    __shared__ bool  is_last;
    int lane = tid & 31;
    int wid  = tid >> 5;
    if (lane == 0) warp_sums[wid] = sum;
    __syncthreads();

    if (wid == 0) {
        float s = (lane < THREADS / 32) ? warp_sums[lane] : 0.0f;
        #pragma unroll
        for (int off = 16; off > 0; off >>= 1)
            s += __shfl_down_sync(0xFFFFFFFFu, s, off);
        if (lane == 0) {
            g_partials[blockIdx.x] = s;
            __threadfence();
            unsigned int t = atomicAdd(&g_ticket, 1u);
            is_last = (t == (unsigned int)(gridDim.x - 1));
        }
    }
    __syncthreads();

    // Last block sums all partials in a FIXED order -> deterministic.
    if (is_last) {
        float fs = 0.0f;
        for (int k = tid; k < BLOCKS; k += THREADS)
            fs += *((volatile float*)&g_partials[k]);

        #pragma unroll
        for (int off = 16; off > 0; off >>= 1)
            fs += __shfl_down_sync(0xFFFFFFFFu, fs, off);

        if (lane == 0) warp_sums[wid] = fs;
        __syncthreads();

        if (wid == 0) {
            float s = (lane < THREADS / 32) ? warp_sums[lane] : 0.0f;
            #pragma unroll
            for (int off = 16; off > 0; off >>= 1)
                s += __shfl_down_sync(0xFFFFFFFFu, s, off);
            if (lane == 0) {
                out[0] = s * inv_n;
                g_ticket = 0;   // reset for next graph replay
            }
        }
    }
}

extern "C" void kernel_launch(void* const* d_in, const int* in_sizes, int n_in,
                              void* d_out, int out_size)
{
    const float* pred = (const float*)d_in[0];
    const int*   tgt  = (const int*)d_in[1];
    float*       out  = (float*)d_out;
    int n = in_sizes[0];

    int n_vec   = n / 4;            // 2^23 float4s
    int n_tiles = n_vec / TILE_V4;  // 16384 tiles (exact for N = 2^25)

    // Unconditional (idempotent, capture-legal): no static guards allowed.
    cudaFuncSetAttribute(wmse_bulk_kernel,
                         cudaFuncAttributeMaxDynamicSharedMemorySize, SMEM_SIZE);

    wmse_bulk_kernel<<<BLOCKS, THREADS, SMEM_SIZE>>>(
        (const float4*)pred, (const int4*)tgt, out, n_tiles, 1.0f / (float)n);
}